// round 8
// baseline (speedup 1.0000x reference)
#include <cuda_runtime.h>
#include <math.h>
#include <float.h>

// Problem constants
#define Bz   4
#define Nn   4096
#define DIMc 1024
#define Hh   16
#define DHh  64
#define Mm   32

#define NORMALIZER 0.3535533905932738f   // 64^-0.25
#define DIAGC      0.0625f               // 0.5 * 64^-0.5
#define RATIO      0.17676766f
#undef RATIO
#define RATIO      0.17677669529663687f  // 32^-0.5
#define FEPS       1e-4f

// ---------------- scratch (device globals: no allocation allowed) -------------
__device__ float g_q   [Bz*Nn*DIMc];
__device__ float g_k   [Bz*Nn*DIMc];
__device__ float g_v   [Bz*Nn*DIMc];
__device__ float g_attn[Bz*Nn*DIMc];
__device__ float g_qf  [Bz*Hh*Nn*Mm];
__device__ float g_kf  [Bz*Hh*Nn*Mm];
__device__ float g_kmax[Bz*Hh];
__device__ float g_kcs [Bz*Hh*Mm];
__device__ float g_ctx [Bz*Hh*Mm*DHh];

// ---------------- SGEMM: C[Mr,Nc] = A[Mr,K] @ W[K,Nc] + bias, optional row mask
#define BM 128
#define BN 128
#define BK 16
#define TM 8
#define TN 8

__global__ __launch_bounds__(256, 2)
void sgemm_bias_kernel(const float* __restrict__ A, const float* __restrict__ W,
                       const float* __restrict__ bias, float* __restrict__ C,
                       int Mr, int Nc, int Kd,
                       const unsigned char* __restrict__ mask)
{
    __shared__ float As[BK][BM];
    __shared__ float Bs[BK][BN];

    const int tid = threadIdx.x;
    const int bx = blockIdx.x, by = blockIdx.y;
    const int tcol = tid & 15;   // 16 threads across N
    const int trow = tid >> 4;   // 16 threads down M

    const int aRow = tid >> 2;          // 0..63 (two passes -> 128 rows)
    const int aCol = (tid & 3) << 2;    // 0,4,8,12
    const int bRow = tid >> 5;          // 0..7  (two passes -> 16 rows)
    const int bCol = (tid & 31) << 2;

    const float* Abase = A + (size_t)(by * BM) * Kd;
    const float* Wbase = W + (size_t)bx * BN;

    float acc[TM][TN];
#pragma unroll
    for (int i = 0; i < TM; i++)
#pragma unroll
        for (int j = 0; j < TN; j++) acc[i][j] = 0.f;

    for (int kk = 0; kk < Kd; kk += BK) {
#pragma unroll
        for (int s = 0; s < 2; s++) {
            int rrow = aRow + 64 * s;
            float4 av = *(const float4*)(Abase + (size_t)rrow * Kd + kk + aCol);
            As[aCol + 0][rrow] = av.x;
            As[aCol + 1][rrow] = av.y;
            As[aCol + 2][rrow] = av.z;
            As[aCol + 3][rrow] = av.w;
        }
#pragma unroll
        for (int s = 0; s < 2; s++) {
            int rrow = bRow + 8 * s;
            float4 bv = *(const float4*)(Wbase + (size_t)(kk + rrow) * Nc + bCol);
            *(float4*)&Bs[rrow][bCol] = bv;
        }
        __syncthreads();

#pragma unroll
        for (int k = 0; k < BK; k++) {
            float4 a0 = *(const float4*)&As[k][trow * TM];
            float4 a1 = *(const float4*)&As[k][trow * TM + 4];
            float4 b0 = *(const float4*)&Bs[k][tcol * TN];
            float4 b1 = *(const float4*)&Bs[k][tcol * TN + 4];
            float ra[8] = {a0.x, a0.y, a0.z, a0.w, a1.x, a1.y, a1.z, a1.w};
            float rb[8] = {b0.x, b0.y, b0.z, b0.w, b1.x, b1.y, b1.z, b1.w};
#pragma unroll
            for (int i = 0; i < TM; i++)
#pragma unroll
                for (int j = 0; j < TN; j++)
                    acc[i][j] = fmaf(ra[i], rb[j], acc[i][j]);
        }
        __syncthreads();
    }

#pragma unroll
    for (int i = 0; i < TM; i++) {
        int row = by * BM + trow * TM + i;
        bool z = (mask != nullptr) && (mask[row] != 0);
#pragma unroll
        for (int j = 0; j < TN; j += 4) {
            int col = bx * BN + tcol * TN + j;
            float4 o;
            o.x = z ? 0.f : acc[i][j + 0] + bias[col + 0];
            o.y = z ? 0.f : acc[i][j + 1] + bias[col + 1];
            o.z = z ? 0.f : acc[i][j + 2] + bias[col + 2];
            o.w = z ? 0.f : acc[i][j + 3] + bias[col + 3];
            *(float4*)&C[(size_t)row * Nc + col] = o;
        }
    }
}

// ---------------- init kmax ----------------
__global__ void init_kmax_kernel() {
    g_kmax[threadIdx.x] = -FLT_MAX;
}

// ---------------- q features: one warp per (b,h,n) row ----------------
__global__ __launch_bounds__(256)
void feature_q_kernel(const float* __restrict__ proj)
{
    __shared__ float projS[Mm][DHh + 1];   // padded: bank-conflict free
    __shared__ float rowS[8][DHh];

    const int tid = threadIdx.x;
    for (int i = tid; i < Mm * DHh; i += 256)
        projS[i >> 6][i & 63] = proj[i];

    const int warp = tid >> 5, lane = tid & 31;
    const int r = blockIdx.x * 8 + warp;          // (b*H + h)*N + n
    const int bh = r >> 12;                        // N = 4096
    const int n  = r & (Nn - 1);
    const int b  = bh >> 4, h = bh & 15;

    const float* qrow = g_q + ((size_t)(b * Nn + n)) * DIMc + h * DHh;
    float q0 = qrow[lane], q1 = qrow[lane + 32];
    rowS[warp][lane]      = q0 * NORMALIZER;
    rowS[warp][lane + 32] = q1 * NORMALIZER;
    float ss = q0 * q0 + q1 * q1;
    __syncthreads();

#pragma unroll
    for (int o = 16; o > 0; o >>= 1) ss += __shfl_xor_sync(0xffffffffu, ss, o);
    float diag = DIAGC * ss;

    float dd = 0.f;
    const float* pr = &projS[lane][0];
#pragma unroll
    for (int d = 0; d < DHh; d++) dd = fmaf(rowS[warp][d], pr[d], dd);

    float mx = dd;
#pragma unroll
    for (int o = 16; o > 0; o >>= 1) mx = fmaxf(mx, __shfl_xor_sync(0xffffffffu, mx, o));

    g_qf[(size_t)r * Mm + lane] = RATIO * (expf(dd - diag - mx) + FEPS);
}

// ---------------- k features pass A: store (dd - diag), track max(dd) per bh ---
__global__ __launch_bounds__(256)
void feature_k_kernel(const float* __restrict__ proj)
{
    __shared__ float projS[Mm][DHh + 1];
    __shared__ float rowS[8][DHh];
    __shared__ float wmax[8];

    const int tid = threadIdx.x;
    for (int i = tid; i < Mm * DHh; i += 256)
        projS[i >> 6][i & 63] = proj[i];

    const int warp = tid >> 5, lane = tid & 31;
    const int r = blockIdx.x * 8 + warp;
    const int bh = r >> 12;
    const int n  = r & (Nn - 1);
    const int b  = bh >> 4, h = bh & 15;

    const float* krow = g_k + ((size_t)(b * Nn + n)) * DIMc + h * DHh;
    float k0 = krow[lane], k1 = krow[lane + 32];
    rowS[warp][lane]      = k0 * NORMALIZER;
    rowS[warp][lane + 32] = k1 * NORMALIZER;
    float ss = k0 * k0 + k1 * k1;
    __syncthreads();

#pragma unroll
    for (int o = 16; o > 0; o >>= 1) ss += __shfl_xor_sync(0xffffffffu, ss, o);
    float diag = DIAGC * ss;

    float dd = 0.f;
    const float* pr = &projS[lane][0];
#pragma unroll
    for (int d = 0; d < DHh; d++) dd = fmaf(rowS[warp][d], pr[d], dd);

    g_kf[(size_t)r * Mm + lane] = dd - diag;

    float mx = dd;
#pragma unroll
    for (int o = 16; o > 0; o >>= 1) mx = fmaxf(mx, __shfl_xor_sync(0xffffffffu, mx, o));
    if (lane == 0) wmax[warp] = mx;
    __syncthreads();

    if (tid == 0) {
        float m = wmax[0];
#pragma unroll
        for (int i = 1; i < 8; i++) m = fmaxf(m, wmax[i]);
        // deterministic atomic max (max is order-independent)
        int* ia = (int*)&g_kmax[bh];
        int old = *ia;
        while (__int_as_float(old) < m) {
            int assumed = old;
            old = atomicCAS(ia, assumed, __float_as_int(m));
            if (old == assumed) break;
        }
    }
}

// ---------------- k features pass B: apply exp with global stab ----------------
__global__ __launch_bounds__(256)
void kf_exp_kernel()
{
    size_t i = (size_t)blockIdx.x * 256 + threadIdx.x;   // total 8388608
    int bh = (int)(i >> 17);                              // N*M = 2^17
    g_kf[i] = RATIO * (expf(g_kf[i] - g_kmax[bh]) + FEPS);
}

// ---------------- k_cumsum: sum over n per (b,h,m), deterministic ----------------
__global__ __launch_bounds__(256)
void kcs_kernel()
{
    const int bh = blockIdx.x;
    const int t = threadIdx.x;
    const int m = t & 31, g = t >> 5;   // 8 partial groups per m
    const float* base = g_kf + (size_t)bh * (Nn * Mm);
    float s = 0.f;
    for (int n = g; n < Nn; n += 8) s += base[(size_t)n * Mm + m];
    __shared__ float sm[8][32];
    sm[g][m] = s;
    __syncthreads();
    if (g == 0) {
        float tot = 0.f;
#pragma unroll
        for (int i = 0; i < 8; i++) tot += sm[i][m];
        g_kcs[bh * Mm + m] = tot;
    }
}

// ---------------- context = kf^T @ v per (b,h): 32x64 output -------------------
__global__ __launch_bounds__(256)
void context_kernel()
{
    const int bh = blockIdx.x, b = bh >> 4, h = bh & 15;
    const int t = threadIdx.x;
    const int e = t & 63, mg = t >> 6;   // thread owns m in {mg, mg+4, ..., mg+28}

    __shared__ float kfS[32][33];
    __shared__ float vS[32][DHh];

    float acc[8];
#pragma unroll
    for (int i = 0; i < 8; i++) acc[i] = 0.f;

    const float* kfb = g_kf + (size_t)bh * (Nn * Mm);
    const float* vb  = g_v  + (size_t)b * Nn * DIMc + h * DHh;

    for (int n0 = 0; n0 < Nn; n0 += 32) {
        for (int i = t; i < 32 * 32; i += 256)
            kfS[i >> 5][i & 31] = kfb[(size_t)(n0 + (i >> 5)) * Mm + (i & 31)];
        for (int i = t; i < 32 * 64; i += 256)
            vS[i >> 6][i & 63] = vb[(size_t)(n0 + (i >> 6)) * DIMc + (i & 63)];
        __syncthreads();
#pragma unroll
        for (int nn = 0; nn < 32; nn++) {
            float vv = vS[nn][e];
#pragma unroll
            for (int i = 0; i < 8; i++)
                acc[i] = fmaf(kfS[nn][mg + 4 * i], vv, acc[i]);
        }
        __syncthreads();
    }
#pragma unroll
    for (int i = 0; i < 8; i++)
        g_ctx[(size_t)bh * (Mm * DHh) + (mg + 4 * i) * DHh + e] = acc[i];
}

// ---------------- per-row output: out = D_inv * (qf @ ctx), merge heads ---------
__global__ __launch_bounds__(256)
void attn_out_kernel()
{
    __shared__ float ctxS[Mm][DHh];
    __shared__ float kcsS[Mm];

    const int tid = threadIdx.x;
    const int warp = tid >> 5, lane = tid & 31;
    const int r = blockIdx.x * 8 + warp;
    const int bh = r >> 12;
    const int n  = r & (Nn - 1);
    const int b  = bh >> 4, h = bh & 15;

    for (int i = tid; i < Mm * DHh; i += 256)
        ctxS[i >> 6][i & 63] = g_ctx[(size_t)bh * (Mm * DHh) + i];
    if (tid < Mm) kcsS[tid] = g_kcs[bh * Mm + tid];
    __syncthreads();

    float myqf = g_qf[(size_t)r * Mm + lane];
    float D = myqf * kcsS[lane];
#pragma unroll
    for (int o = 16; o > 0; o >>= 1) D += __shfl_xor_sync(0xffffffffu, D, o);
    float Dinv = 1.0f / D;

    float o0 = 0.f, o1 = 0.f;
#pragma unroll
    for (int m = 0; m < Mm; m++) {
        float qv = __shfl_sync(0xffffffffu, myqf, m);
        o0 = fmaf(qv, ctxS[m][lane], o0);
        o1 = fmaf(qv, ctxS[m][lane + 32], o1);
    }
    float* op = g_attn + (size_t)(b * Nn + n) * DIMc + h * DHh;
    op[lane]      = Dinv * o0;
    op[lane + 32] = Dinv * o1;
}

// ---------------- launch ----------------
extern "C" void kernel_launch(void* const* d_in, const int* in_sizes, int n_in,
                              void* d_out, int out_size)
{
    const float*         x    = (const float*)d_in[0];
    const unsigned char* mask = (const unsigned char*)d_in[1];
    const float*         proj = (const float*)d_in[2];
    const float* Wq = (const float*)d_in[3];
    const float* bq = (const float*)d_in[4];
    const float* Wk = (const float*)d_in[5];
    const float* bk = (const float*)d_in[6];
    const float* Wv = (const float*)d_in[7];
    const float* bv = (const float*)d_in[8];
    const float* Wo = (const float*)d_in[9];
    const float* bo = (const float*)d_in[10];
    float* out = (float*)d_out;

    float *q_, *k_, *v_, *attn_;
    cudaGetSymbolAddress((void**)&q_,    g_q);
    cudaGetSymbolAddress((void**)&k_,    g_k);
    cudaGetSymbolAddress((void**)&v_,    g_v);
    cudaGetSymbolAddress((void**)&attn_, g_attn);

    const int Mr = Bz * Nn;          // 16384
    const int Nc = DIMc;             // 1024
    const int Kd = DIMc;             // 1024
    dim3 gGemm(Nc / BN, Mr / BM);    // (8, 128)

    init_kmax_kernel<<<1, Bz * Hh>>>();

    sgemm_bias_kernel<<<gGemm, 256>>>(x, Wq, bq, q_, Mr, Nc, Kd, nullptr);
    sgemm_bias_kernel<<<gGemm, 256>>>(x, Wk, bk, k_, Mr, Nc, Kd, nullptr);
    sgemm_bias_kernel<<<gGemm, 256>>>(x, Wv, bv, v_, Mr, Nc, Kd, mask);

    const int rowBlocks = (Bz * Hh * Nn) / 8;     // 32768
    feature_q_kernel<<<rowBlocks, 256>>>(proj);
    feature_k_kernel<<<rowBlocks, 256>>>(proj);

    kf_exp_kernel<<<(Bz * Hh * Nn * Mm) / 256, 256>>>();
    kcs_kernel<<<Bz * Hh, 256>>>();
    context_kernel<<<Bz * Hh, 256>>>();
    attn_out_kernel<<<rowBlocks, 256>>>();

    sgemm_bias_kernel<<<gGemm, 256>>>(attn_, Wo, bo, out, Mr, Nc, Kd, nullptr);
}

// round 12
// speedup vs baseline: 2.6402x; 2.6402x over previous
#include <cuda_runtime.h>
#include <cuda_bf16.h>
#include <math.h>
#include <float.h>
#include <stdint.h>

// Problem constants
#define Bz   4
#define Nn   4096
#define DIMc 1024
#define Hh   16
#define DHh  64
#define Mm   32

#define NORMALIZER 0.3535533905932738f   // 64^-0.25
#define DIAGC      0.0625f               // 0.5 * 64^-0.5
#define RATIO      0.17677669529663687f  // 32^-0.5
#define FEPS       1e-4f

#define NSEG 16

// ---------------- scratch (device globals: no allocation allowed) -------------
__device__ float g_q   [Bz*Nn*DIMc];
__device__ float g_k   [Bz*Nn*DIMc];
__device__ float g_v   [Bz*Nn*DIMc];
__device__ float g_attn[Bz*Nn*DIMc];
__device__ float g_qf  [Bz*Hh*Nn*Mm];
__device__ float g_kf  [Bz*Hh*Nn*Mm];
__device__ float g_kmax[Bz*Hh];
__device__ float g_kcs [Bz*Hh*Mm];
__device__ float g_ctx [Bz*Hh*Mm*DHh];
__device__ float g_ctxp[Bz*Hh*NSEG*Mm*DHh];

// bf16 hi/lo splits: A operand (x, later reused for attn) + 4 transposed weights
__device__ __nv_bfloat16 g_xh [Bz*Nn*DIMc];
__device__ __nv_bfloat16 g_xl [Bz*Nn*DIMc];
__device__ __nv_bfloat16 g_wth[4*DIMc*DIMc];
__device__ __nv_bfloat16 g_wtl[4*DIMc*DIMc];

// ==================== helpers ====================
__device__ __forceinline__ uint32_t smem_u32(const void* p) {
    uint32_t a;
    asm("{ .reg .u64 t; cvta.to.shared.u64 t, %1; cvt.u32.u64 %0, t; }" : "=r"(a) : "l"(p));
    return a;
}
__device__ __forceinline__ void cp_async16(uint32_t saddr, const void* gaddr) {
    asm volatile("cp.async.cg.shared.global [%0], [%1], 16;" :: "r"(saddr), "l"(gaddr));
}
__device__ __forceinline__ void cp_commit() {
    asm volatile("cp.async.commit_group;" ::: "memory");
}
__device__ __forceinline__ void cp_wait2() {
    asm volatile("cp.async.wait_group 2;" ::: "memory");
}
__device__ __forceinline__ void ldmatrix_x4(uint32_t* r, uint32_t addr) {
    asm volatile("ldmatrix.sync.aligned.m8n8.x4.shared.b16 {%0,%1,%2,%3}, [%4];"
                 : "=r"(r[0]), "=r"(r[1]), "=r"(r[2]), "=r"(r[3]) : "r"(addr));
}
__device__ __forceinline__ void mma16816(float* d, const uint32_t* a, const uint32_t* b) {
    asm volatile(
        "mma.sync.aligned.m16n8k16.row.col.f32.bf16.bf16.f32 "
        "{%0,%1,%2,%3}, {%4,%5,%6,%7}, {%8,%9}, {%0,%1,%2,%3};"
        : "+f"(d[0]), "+f"(d[1]), "+f"(d[2]), "+f"(d[3])
        : "r"(a[0]), "r"(a[1]), "r"(a[2]), "r"(a[3]), "r"(b[0]), "r"(b[1]));
}

// ==================== split conversion kernels ====================
__global__ __launch_bounds__(256)
void split_kernel(const float4* __restrict__ in,
                  __nv_bfloat162* __restrict__ hi, __nv_bfloat162* __restrict__ lo)
{
    int i = blockIdx.x * 256 + threadIdx.x;
    float4 v = in[i];
    __nv_bfloat162 h0, h1, l0, l1;
    h0.x = __float2bfloat16_rn(v.x); l0.x = __float2bfloat16_rn(v.x - __bfloat162float(h0.x));
    h0.y = __float2bfloat16_rn(v.y); l0.y = __float2bfloat16_rn(v.y - __bfloat162float(h0.y));
    h1.x = __float2bfloat16_rn(v.z); l1.x = __float2bfloat16_rn(v.z - __bfloat162float(h1.x));
    h1.y = __float2bfloat16_rn(v.w); l1.y = __float2bfloat16_rn(v.w - __bfloat162float(h1.y));
    hi[2*i] = h0; hi[2*i+1] = h1;
    lo[2*i] = l0; lo[2*i+1] = l1;
}

// W[K,N] fp32 -> Wt[N,K] bf16 hi/lo (transpose + split)
__global__ __launch_bounds__(256)
void splitT_kernel(const float* __restrict__ W,
                   __nv_bfloat16* __restrict__ th, __nv_bfloat16* __restrict__ tl)
{
    __shared__ float t[32][33];
    int tx = threadIdx.x & 31, ty = threadIdx.x >> 5;
    int k0 = blockIdx.y * 32, n0 = blockIdx.x * 32;
#pragma unroll
    for (int r = 0; r < 4; r++)
        t[ty + r*8][tx] = W[(size_t)(k0 + ty + r*8) * DIMc + n0 + tx];
    __syncthreads();
#pragma unroll
    for (int r = 0; r < 4; r++) {
        int n = n0 + ty + r*8, k = k0 + tx;
        float v = t[tx][ty + r*8];
        __nv_bfloat16 h = __float2bfloat16_rn(v);
        __nv_bfloat16 l = __float2bfloat16_rn(v - __bfloat162float(h));
        th[(size_t)n * DIMc + k] = h;
        tl[(size_t)n * DIMc + k] = l;
    }
}

// ==================== bf16 mma.sync GEMM ====================
// C[16384,1024] = (Ah+Al)[16384,1024] @ (Bth+Btl)^T + bias
// 3 passes: Ah*Bh + Al*Bh + Ah*Bl, all accumulated in fp32 registers.
// Tile: BM=128, BN=128, BK=64 (bf16). 8 warps (2M x 4N), warp tile 64x32.
// 3-stage cp.async pipeline. Stage = A(16KB) + B(16KB) = 32KB; 3 stages = 96KB.
#define GEMM_SMEM_BYTES (3 * 32768)
#define NIT 48   // 3 passes * 16 k-tiles

__global__ __launch_bounds__(256)
void gemm_mma_kernel(const __nv_bfloat16* __restrict__ Ah, const __nv_bfloat16* __restrict__ Al,
                     const __nv_bfloat16* __restrict__ Bth, const __nv_bfloat16* __restrict__ Btl,
                     const float* __restrict__ bias, float* __restrict__ C,
                     const unsigned char* __restrict__ mask)
{
    extern __shared__ __align__(1024) char smem[];
    const uint32_t sb = smem_u32(smem);
    const int tid = threadIdx.x, wid = tid >> 5, lane = tid & 31;
    const int wm = wid & 1, wn = wid >> 1;

    const int arow0 = blockIdx.y * 128;
    const int brow0 = blockIdx.x * 128;

    float acc[4][4][4];
#pragma unroll
    for (int i = 0; i < 4; i++)
#pragma unroll
        for (int j = 0; j < 4; j++)
#pragma unroll
            for (int v = 0; v < 4; v++) acc[i][j][v] = 0.f;

    // per-thread load slots: 4 chunks for A, 4 for B (1024 chunks each / 256 thr)
    int lrow[4], lc[4];
    uint32_t lsw[4];
#pragma unroll
    for (int i = 0; i < 4; i++) {
        int q = tid + i * 256;
        lrow[i] = q >> 3; lc[i] = q & 7;
        lsw[i] = (uint32_t)(lrow[i] * 128 + ((lc[i] ^ (lrow[i] & 7)) << 4));
    }

    auto load_stage = [&](int it, int stage) {
        const int p = it >> 4, kt = it & 15, k0 = kt * 64;
        const __nv_bfloat16* Asrc = (p == 1) ? Al : Ah;
        const __nv_bfloat16* Bsrc = (p == 2) ? Btl : Bth;
        const __nv_bfloat16* Ag = Asrc + (size_t)arow0 * DIMc + k0;
        const __nv_bfloat16* Bg = Bsrc + (size_t)brow0 * DIMc + k0;
        uint32_t aS = sb + stage * 32768;
        uint32_t bS = aS + 16384;
#pragma unroll
        for (int i = 0; i < 4; i++) {
            cp_async16(aS + lsw[i], Ag + (size_t)lrow[i] * DIMc + lc[i] * 8);
            cp_async16(bS + lsw[i], Bg + (size_t)lrow[i] * DIMc + lc[i] * 8);
        }
        cp_commit();
    };

    // ldmatrix lane addressing (computed once):
    // A: row = wm*64 + mt*16 + (lane&7) + ((lane>>3)&1)*8 ; chunk = c0 + (lane>>4)
    const int a_r = wm * 64 + (lane & 7) + ((lane >> 3) & 1) * 8;
    const int a_cx = (lane >> 4);
    // B: n = wn*32 + ntp*16 + ((lane>>4)<<3) + (lane&7) ; chunk = c0 + ((lane>>3)&1)
    const int b_r = wn * 32 + ((lane >> 4) << 3) + (lane & 7);
    const int b_cx = (lane >> 3) & 1;

    load_stage(0, 0);
    load_stage(1, 1);

    for (int it = 0; it < NIT; ++it) {
        if (it + 2 < NIT) load_stage(it + 2, (it + 2) % 3);
        cp_wait2();
        __syncthreads();

        const int stage = it % 3;
        const uint32_t aS = sb + stage * 32768;
        const uint32_t bS = aS + 16384;

#pragma unroll
        for (int kk = 0; kk < 4; ++kk) {
            const int c0 = kk * 2;
            uint32_t af[4][4], bf[4][2];
#pragma unroll
            for (int mt = 0; mt < 4; ++mt) {
                int row = a_r + mt * 16;
                int ch = c0 + a_cx;
                ldmatrix_x4(af[mt], aS + (uint32_t)(row * 128 + ((ch ^ (row & 7)) << 4)));
            }
#pragma unroll
            for (int ntp = 0; ntp < 2; ++ntp) {
                int row = b_r + ntp * 16;
                int ch = c0 + b_cx;
                uint32_t r4[4];
                ldmatrix_x4(r4, bS + (uint32_t)(row * 128 + ((ch ^ (row & 7)) << 4)));
                bf[2*ntp][0] = r4[0]; bf[2*ntp][1] = r4[1];
                bf[2*ntp+1][0] = r4[2]; bf[2*ntp+1][1] = r4[3];
            }
#pragma unroll
            for (int mt = 0; mt < 4; ++mt)
#pragma unroll
                for (int nt = 0; nt < 4; ++nt)
                    mma16816(acc[mt][nt], af[mt], bf[nt]);
        }
        __syncthreads();
    }

    // epilogue: bias + optional mask, write fp32
    const int gid = lane >> 2, tig = lane & 3;
#pragma unroll
    for (int mt = 0; mt < 4; ++mt) {
        int r0 = arow0 + wm * 64 + mt * 16 + gid;
        int r1 = r0 + 8;
        bool z0 = (mask != nullptr) && (mask[r0] != 0);
        bool z1 = (mask != nullptr) && (mask[r1] != 0);
#pragma unroll
        for (int nt = 0; nt < 4; ++nt) {
            int col = brow0 + wn * 32 + nt * 8 + tig * 2;
            float b0 = bias[col], b1 = bias[col + 1];
            float2 o0, o1;
            o0.x = z0 ? 0.f : acc[mt][nt][0] + b0;
            o0.y = z0 ? 0.f : acc[mt][nt][1] + b1;
            o1.x = z1 ? 0.f : acc[mt][nt][2] + b0;
            o1.y = z1 ? 0.f : acc[mt][nt][3] + b1;
            *(float2*)&C[(size_t)r0 * DIMc + col] = o0;
            *(float2*)&C[(size_t)r1 * DIMc + col] = o1;
        }
    }
}

// ==================== feature / attention kernels ====================
__global__ void init_kmax_kernel() { g_kmax[threadIdx.x] = -FLT_MAX; }

__global__ __launch_bounds__(256)
void feature_q_kernel(const float* __restrict__ proj)
{
    __shared__ float projS[Mm][DHh + 1];
    __shared__ float rowS[8][DHh];
    const int tid = threadIdx.x;
    for (int i = tid; i < Mm * DHh; i += 256)
        projS[i >> 6][i & 63] = proj[i];

    const int warp = tid >> 5, lane = tid & 31;
    const int r = blockIdx.x * 8 + warp;
    const int bh = r >> 12;
    const int n  = r & (Nn - 1);
    const int b  = bh >> 4, h = bh & 15;

    const float* qrow = g_q + ((size_t)(b * Nn + n)) * DIMc + h * DHh;
    float q0 = qrow[lane], q1 = qrow[lane + 32];
    rowS[warp][lane]      = q0 * NORMALIZER;
    rowS[warp][lane + 32] = q1 * NORMALIZER;
    float ss = q0 * q0 + q1 * q1;
    __syncthreads();
#pragma unroll
    for (int o = 16; o > 0; o >>= 1) ss += __shfl_xor_sync(0xffffffffu, ss, o);
    float diag = DIAGC * ss;

    float dd = 0.f;
    const float* pr = &projS[lane][0];
#pragma unroll
    for (int d = 0; d < DHh; d++) dd = fmaf(rowS[warp][d], pr[d], dd);

    float mx = dd;
#pragma unroll
    for (int o = 16; o > 0; o >>= 1) mx = fmaxf(mx, __shfl_xor_sync(0xffffffffu, mx, o));
    g_qf[(size_t)r * Mm + lane] = RATIO * (expf(dd - diag - mx) + FEPS);
}

__global__ __launch_bounds__(256)
void feature_k_kernel(const float* __restrict__ proj)
{
    __shared__ float projS[Mm][DHh + 1];
    __shared__ float rowS[8][DHh];
    __shared__ float wmax[8];
    const int tid = threadIdx.x;
    for (int i = tid; i < Mm * DHh; i += 256)
        projS[i >> 6][i & 63] = proj[i];

    const int warp = tid >> 5, lane = tid & 31;
    const int r = blockIdx.x * 8 + warp;
    const int bh = r >> 12;
    const int n  = r & (Nn - 1);
    const int b  = bh >> 4, h = bh & 15;

    const float* krow = g_k + ((size_t)(b * Nn + n)) * DIMc + h * DHh;
    float k0 = krow[lane], k1 = krow[lane + 32];
    rowS[warp][lane]      = k0 * NORMALIZER;
    rowS[warp][lane + 32] = k1 * NORMALIZER;
    float ss = k0 * k0 + k1 * k1;
    __syncthreads();
#pragma unroll
    for (int o = 16; o > 0; o >>= 1) ss += __shfl_xor_sync(0xffffffffu, ss, o);
    float diag = DIAGC * ss;

    float dd = 0.f;
    const float* pr = &projS[lane][0];
#pragma unroll
    for (int d = 0; d < DHh; d++) dd = fmaf(rowS[warp][d], pr[d], dd);

    g_kf[(size_t)r * Mm + lane] = dd - diag;

    float mx = dd;
#pragma unroll
    for (int o = 16; o > 0; o >>= 1) mx = fmaxf(mx, __shfl_xor_sync(0xffffffffu, mx, o));
    if (lane == 0) wmax[warp] = mx;
    __syncthreads();
    if (tid == 0) {
        float m = wmax[0];
#pragma unroll
        for (int i = 1; i < 8; i++) m = fmaxf(m, wmax[i]);
        int* ia = (int*)&g_kmax[bh];
        int old = *ia;
        while (__int_as_float(old) < m) {
            int assumed = old;
            old = atomicCAS(ia, assumed, __float_as_int(m));
            if (old == assumed) break;
        }
    }
}

__global__ __launch_bounds__(256)
void kf_exp_kernel()
{
    size_t i = (size_t)blockIdx.x * 256 + threadIdx.x;
    int bh = (int)(i >> 17);
    g_kf[i] = RATIO * (expf(g_kf[i] - g_kmax[bh]) + FEPS);
}

__global__ __launch_bounds__(256)
void kcs_kernel()
{
    const int bh = blockIdx.x;
    const int t = threadIdx.x;
    const int m = t & 31, g = t >> 5;
    const float* base = g_kf + (size_t)bh * (Nn * Mm);
    float s = 0.f;
    for (int n = g; n < Nn; n += 8) s += base[(size_t)n * Mm + m];
    __shared__ float sm[8][32];
    sm[g][m] = s;
    __syncthreads();
    if (g == 0) {
        float tot = 0.f;
#pragma unroll
        for (int i = 0; i < 8; i++) tot += sm[i][m];
        g_kcs[bh * Mm + m] = tot;
    }
}

// context = kf^T @ v per (b,h), split across NSEG n-segments
__global__ __launch_bounds__(256)
void context_part_kernel()
{
    const int bh = blockIdx.x, seg = blockIdx.y;
    const int b = bh >> 4, h = bh & 15;
    const int t = threadIdx.x;
    const int e = t & 63, mg = t >> 6;

    __shared__ float kfS[32][33];
    __shared__ float vS[32][DHh];

    float acc[8];
#pragma unroll
    for (int i = 0; i < 8; i++) acc[i] = 0.f;

    const float* kfb = g_kf + (size_t)bh * (Nn * Mm);
    const float* vb  = g_v  + (size_t)b * Nn * DIMc + h * DHh;
    const int nbeg = seg * (Nn / NSEG);

    for (int n0 = nbeg; n0 < nbeg + Nn / NSEG; n0 += 32) {
        for (int i = t; i < 32 * 32; i += 256)
            kfS[i >> 5][i & 31] = kfb[(size_t)(n0 + (i >> 5)) * Mm + (i & 31)];
        for (int i = t; i < 32 * 64; i += 256)
            vS[i >> 6][i & 63] = vb[(size_t)(n0 + (i >> 6)) * DIMc + (i & 63)];
        __syncthreads();
#pragma unroll
        for (int nn = 0; nn < 32; nn++) {
            float vv = vS[nn][e];
#pragma unroll
            for (int i = 0; i < 8; i++)
                acc[i] = fmaf(kfS[nn][mg + 4 * i], vv, acc[i]);
        }
        __syncthreads();
    }
#pragma unroll
    for (int i = 0; i < 8; i++)
        g_ctxp[((size_t)bh * NSEG + seg) * (Mm * DHh) + (mg + 4 * i) * DHh + e] = acc[i];
}

__global__ __launch_bounds__(256)
void ctx_reduce_kernel()
{
    const int bh = blockIdx.x;
    for (int i = threadIdx.x; i < Mm * DHh; i += 256) {
        float s = 0.f;
#pragma unroll
        for (int g = 0; g < NSEG; g++)
            s += g_ctxp[((size_t)bh * NSEG + g) * (Mm * DHh) + i];
        g_ctx[(size_t)bh * (Mm * DHh) + i] = s;
    }
}

__global__ __launch_bounds__(256)
void attn_out_kernel()
{
    __shared__ float ctxS[Mm][DHh];
    __shared__ float kcsS[Mm];

    const int tid = threadIdx.x;
    const int warp = tid >> 5, lane = tid & 31;
    const int r = blockIdx.x * 8 + warp;
    const int bh = r >> 12;
    const int n  = r & (Nn - 1);
    const int b  = bh >> 4, h = bh & 15;

    for (int i = tid; i < Mm * DHh; i += 256)
        ctxS[i >> 6][i & 63] = g_ctx[(size_t)bh * (Mm * DHh) + i];
    if (tid < Mm) kcsS[tid] = g_kcs[bh * Mm + tid];
    __syncthreads();

    float myqf = g_qf[(size_t)r * Mm + lane];
    float D = myqf * kcsS[lane];
#pragma unroll
    for (int o = 16; o > 0; o >>= 1) D += __shfl_xor_sync(0xffffffffu, D, o);
    float Dinv = 1.0f / D;

    float o0 = 0.f, o1 = 0.f;
#pragma unroll
    for (int m = 0; m < Mm; m++) {
        float qv = __shfl_sync(0xffffffffu, myqf, m);
        o0 = fmaf(qv, ctxS[m][lane], o0);
        o1 = fmaf(qv, ctxS[m][lane + 32], o1);
    }
    float* op = g_attn + (size_t)(b * Nn + n) * DIMc + h * DHh;
    op[lane]      = Dinv * o0;
    op[lane + 32] = Dinv * o1;
}

// ==================== launch ====================
extern "C" void kernel_launch(void* const* d_in, const int* in_sizes, int n_in,
                              void* d_out, int out_size)
{
    const float*         x    = (const float*)d_in[0];
    const unsigned char* mask = (const unsigned char*)d_in[1];
    const float*         proj = (const float*)d_in[2];
    const float* Wq = (const float*)d_in[3];
    const float* bq = (const float*)d_in[4];
    const float* Wk = (const float*)d_in[5];
    const float* bk = (const float*)d_in[6];
    const float* Wv = (const float*)d_in[7];
    const float* bv = (const float*)d_in[8];
    const float* Wo = (const float*)d_in[9];
    const float* bo = (const float*)d_in[10];
    float* out = (float*)d_out;

    float *q_, *k_, *v_, *attn_;
    __nv_bfloat16 *xh_, *xl_, *wth_, *wtl_;
    cudaGetSymbolAddress((void**)&q_,    g_q);
    cudaGetSymbolAddress((void**)&k_,    g_k);
    cudaGetSymbolAddress((void**)&v_,    g_v);
    cudaGetSymbolAddress((void**)&attn_, g_attn);
    cudaGetSymbolAddress((void**)&xh_,   g_xh);
    cudaGetSymbolAddress((void**)&xl_,   g_xl);
    cudaGetSymbolAddress((void**)&wth_,  g_wth);
    cudaGetSymbolAddress((void**)&wtl_,  g_wtl);

    cudaFuncSetAttribute(gemm_mma_kernel,
                         cudaFuncAttributeMaxDynamicSharedMemorySize, GEMM_SMEM_BYTES);

    const size_t WSZ = (size_t)DIMc * DIMc;
    const int nElem = Bz * Nn * DIMc;
    dim3 gSplitT(32, 32);
    dim3 gGemm(DIMc / 128, (Bz * Nn) / 128);   // (8, 128)

    // conversions
    split_kernel<<<nElem / (256 * 4), 256>>>((const float4*)x,
        (__nv_bfloat162*)xh_, (__nv_bfloat162*)xl_);
    splitT_kernel<<<gSplitT, 256>>>(Wq, wth_ + 0*WSZ, wtl_ + 0*WSZ);
    splitT_kernel<<<gSplitT, 256>>>(Wk, wth_ + 1*WSZ, wtl_ + 1*WSZ);
    splitT_kernel<<<gSplitT, 256>>>(Wv, wth_ + 2*WSZ, wtl_ + 2*WSZ);
    splitT_kernel<<<gSplitT, 256>>>(Wo, wth_ + 3*WSZ, wtl_ + 3*WSZ);
    init_kmax_kernel<<<1, Bz * Hh>>>();

    // projections (tensor cores via mma.sync)
    gemm_mma_kernel<<<gGemm, 256, GEMM_SMEM_BYTES>>>(xh_, xl_, wth_ + 0*WSZ, wtl_ + 0*WSZ, bq, q_, nullptr);
    gemm_mma_kernel<<<gGemm, 256, GEMM_SMEM_BYTES>>>(xh_, xl_, wth_ + 1*WSZ, wtl_ + 1*WSZ, bk, k_, nullptr);
    gemm_mma_kernel<<<gGemm, 256, GEMM_SMEM_BYTES>>>(xh_, xl_, wth_ + 2*WSZ, wtl_ + 2*WSZ, bv, v_, mask);

    // performer attention
    const int rowBlocks = (Bz * Hh * Nn) / 8;
    feature_q_kernel<<<rowBlocks, 256>>>(proj);
    feature_k_kernel<<<rowBlocks, 256>>>(proj);
    kf_exp_kernel<<<(Bz * Hh * Nn * Mm) / 256, 256>>>();
    kcs_kernel<<<Bz * Hh, 256>>>();
    context_part_kernel<<<dim3(Bz * Hh, NSEG), 256>>>();
    ctx_reduce_kernel<<<Bz * Hh, 256>>>();
    attn_out_kernel<<<rowBlocks, 256>>>();

    // output projection (reuse x split buffers for attn)
    split_kernel<<<nElem / (256 * 4), 256>>>((const float4*)attn_,
        (__nv_bfloat162*)xh_, (__nv_bfloat162*)xl_);
    gemm_mma_kernel<<<gGemm, 256, GEMM_SMEM_BYTES>>>(xh_, xl_, wth_ + 3*WSZ, wtl_ + 3*WSZ, bo, out, nullptr);
}